// round 9
// baseline (speedup 1.0000x reference)
#include <cuda_runtime.h>

#define NN 50000
#define DD 128
#define EE 800000

// Scratch (allocation-free rule: __device__ globals)
__device__ float g_fj[NN * DD];
__device__ float g_a1[NN];
__device__ float g_a2[NN];
__device__ int   g_deg[NN];
__device__ int   g_off[NN + 1];
__device__ int   g_pos[NN];
__device__ int   g_col[EE];

__device__ __forceinline__ unsigned long long pack2(float a) {
    unsigned long long r;
    asm("mov.b64 %0, {%1, %1};" : "=l"(r) : "f"(a));
    return r;
}
__device__ __forceinline__ void unpack2(unsigned long long v, float& lo, float& hi) {
    asm("mov.b64 {%0, %1}, %2;" : "=f"(lo), "=f"(hi) : "l"(v));
}
__device__ __forceinline__ unsigned long long ffma2(unsigned long long a,
                                                    unsigned long long b,
                                                    unsigned long long c) {
    unsigned long long d;
    asm("fma.rn.f32x2 %0, %1, %2, %3;" : "=l"(d) : "l"(a), "l"(b), "l"(c));
    return d;
}

// ---------------------------------------------------------------------------
// CSR build (runs on side stream, overlapped with the GEMM)
// ---------------------------------------------------------------------------
__global__ void k_zero() {
    int i = blockIdx.x * 256 + threadIdx.x;
    if (i < NN) g_deg[i] = 0;
}

__global__ void k_count(const int* __restrict__ ei) {
    int e = blockIdx.x * 256 + threadIdx.x;
    if (e < EE) atomicAdd(&g_deg[__ldg(ei + e)], 1);
}

__global__ __launch_bounds__(1024) void k_scan() {
    __shared__ int part[1024];
    const int t = threadIdx.x;
    const int CH = 49;                 // 1024*49 = 50176 >= NN
    const int start = t * CH;
    int sum = 0;
    for (int i = 0; i < CH; i++) {
        int idx = start + i;
        if (idx < NN) sum += g_deg[idx];
    }
    part[t] = sum;
    __syncthreads();
    for (int off = 1; off < 1024; off <<= 1) {
        int tmp = (t >= off) ? part[t - off] : 0;
        __syncthreads();
        part[t] += tmp;
        __syncthreads();
    }
    int run = part[t] - sum;           // exclusive prefix of this chunk
    for (int i = 0; i < CH; i++) {
        int idx = start + i;
        if (idx < NN) {
            g_off[idx] = run;
            g_pos[idx] = run;
            run += g_deg[idx];
        }
    }
    if (t == 1023) g_off[NN] = part[1023];
}

__global__ void k_scatter(const int* __restrict__ ei) {
    int e = blockIdx.x * 256 + threadIdx.x;
    if (e < EE) {
        int r = __ldg(ei + e);
        int c = __ldg(ei + EE + e);
        int p = atomicAdd(&g_pos[r], 1);
        g_col[p] = c;
    }
}

// ---------------------------------------------------------------------------
// Kernel 1: fused dense part (R8-proven f32x2 GEMM, at the fp32 roofline).
//   fi = relu(X W1^T + b1), fj = relu(X W2^T + b2)
//   a1 = fi.wa1 + ba1,      a2 = fj.wa2 + ba2
//   out = fi + sigmoid(a1 + a2) * fj   (self-loop folded)
// ---------------------------------------------------------------------------
__global__ __launch_bounds__(512, 1) void gat_gemm(
    const float* __restrict__ X,
    const float* __restrict__ W1, const float* __restrict__ b1,
    const float* __restrict__ W2, const float* __restrict__ b2,
    const float* __restrict__ wa1, const float* __restrict__ ba1,
    const float* __restrict__ wa2, const float* __restrict__ ba2,
    float* __restrict__ out)
{
    extern __shared__ float smem[];
    float* sA = smem;              // [128][128]
    float* sB = smem + 128 * 128;  // [128][256] : sB[k][j] = W[j][k]

    const int tid = threadIdx.x;
    const int block_row = blockIdx.x * 128;

    for (int i = tid; i < 128 * 32; i += 512) {
        int row = i >> 5, c4 = i & 31;
        float4 v = make_float4(0.f, 0.f, 0.f, 0.f);
        int grow = block_row + row;
        if (grow < NN) v = ((const float4*)X)[grow * 32 + c4];
        ((float4*)sA)[row * 32 + c4] = v;
    }
    for (int i = tid; i < 128 * 32; i += 512) {
        int j = i & 127;
        int k = (i >> 7) << 2;
        float4 v = ((const float4*)W1)[(j * 128 + k) >> 2];
        sB[(k + 0) * 256 + j] = v.x;
        sB[(k + 1) * 256 + j] = v.y;
        sB[(k + 2) * 256 + j] = v.z;
        sB[(k + 3) * 256 + j] = v.w;
        float4 w = ((const float4*)W2)[(j * 128 + k) >> 2];
        sB[(k + 0) * 256 + 128 + j] = w.x;
        sB[(k + 1) * 256 + 128 + j] = w.y;
        sB[(k + 2) * 256 + 128 + j] = w.z;
        sB[(k + 3) * 256 + 128 + j] = w.w;
    }
    __syncthreads();

    const int tx = tid & 31;
    const int ty = tid >> 5;

    unsigned long long acc[8][4];
    #pragma unroll
    for (int r = 0; r < 8; r++)
        #pragma unroll
        for (int p = 0; p < 4; p++) acc[r][p] = 0ull;

    const float* aBase = sA + (ty * 8) * 128;
    const float* bBase = sB + 2 * tx;

    #pragma unroll 2
    for (int k = 0; k < 128; k += 2) {
        unsigned long long bq0[4], bq1[4];
        #pragma unroll
        for (int p = 0; p < 4; p++) {
            bq0[p] = *(const unsigned long long*)(bBase + (k + 0) * 256 + p * 64);
            bq1[p] = *(const unsigned long long*)(bBase + (k + 1) * 256 + p * 64);
        }
        #pragma unroll
        for (int r = 0; r < 8; r++) {
            float2 av = *(const float2*)(aBase + r * 128 + k);
            unsigned long long a0 = pack2(av.x);
            unsigned long long a1p = pack2(av.y);
            #pragma unroll
            for (int p = 0; p < 4; p++) {
                acc[r][p] = ffma2(a0, bq0[p], acc[r][p]);
                acc[r][p] = ffma2(a1p, bq1[p], acc[r][p]);
            }
        }
    }

    const float vba1 = *ba1;
    const float vba2 = *ba2;
    float wv1[4], wv2[4], bv1[4], bv2[4];
    {
        int c0 = 2 * tx, c1 = 2 * tx + 1, c2 = 64 + 2 * tx, c3 = 65 + 2 * tx;
        wv1[0] = wa1[c0]; wv1[1] = wa1[c1]; wv1[2] = wa1[c2]; wv1[3] = wa1[c3];
        wv2[0] = wa2[c0]; wv2[1] = wa2[c1]; wv2[2] = wa2[c2]; wv2[3] = wa2[c3];
        bv1[0] = b1[c0];  bv1[1] = b1[c1];  bv1[2] = b1[c2];  bv1[3] = b1[c3];
        bv2[0] = b2[c0];  bv2[1] = b2[c1];  bv2[2] = b2[c2];  bv2[3] = b2[c3];
    }

    #pragma unroll
    for (int r = 0; r < 8; r++) {
        int grow = block_row + ty * 8 + r;
        if (grow >= NN) continue;
        float fi[4], fj[4];
        unpack2(acc[r][0], fi[0], fi[1]);
        unpack2(acc[r][1], fi[2], fi[3]);
        unpack2(acc[r][2], fj[0], fj[1]);
        unpack2(acc[r][3], fj[2], fj[3]);
        float pa1 = 0.f, pa2 = 0.f;
        #pragma unroll
        for (int i = 0; i < 4; i++) {
            fi[i] = fmaxf(fi[i] + bv1[i], 0.f);
            fj[i] = fmaxf(fj[i] + bv2[i], 0.f);
            pa1 += fi[i] * wv1[i];
            pa2 += fj[i] * wv2[i];
        }
        #pragma unroll
        for (int off = 16; off > 0; off >>= 1) {
            pa1 += __shfl_xor_sync(0xffffffffu, pa1, off);
            pa2 += __shfl_xor_sync(0xffffffffu, pa2, off);
        }
        float A1 = pa1 + vba1;
        float A2 = pa2 + vba2;
        if (tx == 0) { g_a1[grow] = A1; g_a2[grow] = A2; }
        float att = 1.0f / (1.0f + expf(-(A1 + A2)));

        float* orow = out + (size_t)grow * DD;
        float* frow = g_fj + (size_t)grow * DD;
        *(float2*)(orow + 2 * tx)      = make_float2(fi[0] + att * fj[0],
                                                     fi[1] + att * fj[1]);
        *(float2*)(orow + 64 + 2 * tx) = make_float2(fi[2] + att * fj[2],
                                                     fi[3] + att * fj[3]);
        *(float2*)(frow + 2 * tx)      = make_float2(fj[0], fj[1]);
        *(float2*)(frow + 64 + 2 * tx) = make_float2(fj[2], fj[3]);
    }
}

// ---------------------------------------------------------------------------
// Kernel 2: CSR aggregation, warp per node, 4-edge MLP batches, NO atomics.
//   out[r] += sum_{c in in(r)} sigmoid(a1[r] + a2[c]) * fj[c]
// ---------------------------------------------------------------------------
__global__ __launch_bounds__(256) void gat_agg(float* __restrict__ out)
{
    const int warp = threadIdx.x >> 5;
    const int lane = threadIdx.x & 31;
    const int node = blockIdx.x * 8 + warp;
    if (node >= NN) return;

    const int s = g_off[node];
    const int e = g_off[node + 1];
    if (s == e) return;

    const float a1v = g_a1[node];
    float4 acc = make_float4(0.f, 0.f, 0.f, 0.f);

    for (int base = s; base < e; base += 32) {
        const int rem = e - base;
        const int cnt = rem < 32 ? rem : 32;
        int cl = (lane < cnt) ? __ldg(g_col + base + lane) : 0;

        int j = 0;
        #pragma unroll 1
        for (; j + 4 <= cnt; j += 4) {
            const int c0 = __shfl_sync(0xffffffffu, cl, j);
            const int c1 = __shfl_sync(0xffffffffu, cl, j + 1);
            const int c2 = __shfl_sync(0xffffffffu, cl, j + 2);
            const int c3 = __shfl_sync(0xffffffffu, cl, j + 3);
            // 4 independent a2 loads + 4 independent fj row loads in flight
            const float a20 = g_a2[c0];
            const float a21 = g_a2[c1];
            const float a22 = g_a2[c2];
            const float a23 = g_a2[c3];
            const float4 v0 = *(const float4*)(g_fj + (size_t)c0 * DD + lane * 4);
            const float4 v1 = *(const float4*)(g_fj + (size_t)c1 * DD + lane * 4);
            const float4 v2 = *(const float4*)(g_fj + (size_t)c2 * DD + lane * 4);
            const float4 v3 = *(const float4*)(g_fj + (size_t)c3 * DD + lane * 4);
            const float t0 = 1.0f / (1.0f + __expf(-(a1v + a20)));
            const float t1 = 1.0f / (1.0f + __expf(-(a1v + a21)));
            const float t2 = 1.0f / (1.0f + __expf(-(a1v + a22)));
            const float t3 = 1.0f / (1.0f + __expf(-(a1v + a23)));
            acc.x += t0 * v0.x + t1 * v1.x + t2 * v2.x + t3 * v3.x;
            acc.y += t0 * v0.y + t1 * v1.y + t2 * v2.y + t3 * v3.y;
            acc.z += t0 * v0.z + t1 * v1.z + t2 * v2.z + t3 * v3.z;
            acc.w += t0 * v0.w + t1 * v1.w + t2 * v2.w + t3 * v3.w;
        }
        #pragma unroll 1
        for (; j < cnt; j++) {
            const int c = __shfl_sync(0xffffffffu, cl, j);
            const float att = 1.0f / (1.0f + __expf(-(a1v + g_a2[c])));
            const float4 v = *(const float4*)(g_fj + (size_t)c * DD + lane * 4);
            acc.x += att * v.x;
            acc.y += att * v.y;
            acc.z += att * v.z;
            acc.w += att * v.w;
        }
    }

    float* p = out + (size_t)node * DD + lane * 4;
    float4 o = *(const float4*)p;
    o.x += acc.x; o.y += acc.y; o.z += acc.z; o.w += acc.w;
    *(float4*)p = o;
}

// ---------------------------------------------------------------------------

extern "C" void kernel_launch(void* const* d_in, const int* in_sizes, int n_in,
                              void* d_out, int out_size)
{
    const float* X   = (const float*)d_in[0];
    const float* W1  = (const float*)d_in[1];
    const float* b1  = (const float*)d_in[2];
    const float* W2  = (const float*)d_in[3];
    const float* b2  = (const float*)d_in[4];
    const float* wa1 = (const float*)d_in[5];
    const float* ba1 = (const float*)d_in[6];
    const float* wa2 = (const float*)d_in[7];
    const float* ba2 = (const float*)d_in[8];
    const int*   ei  = (const int*)d_in[9];
    float* out = (float*)d_out;

    // One-time setup (host-side resources only; no device memory allocation)
    static cudaStream_t s2;
    static cudaEvent_t evF, evJ;
    static bool inited = false;
    if (!inited) {
        cudaStreamCreateWithFlags(&s2, cudaStreamNonBlocking);
        cudaEventCreateWithFlags(&evF, cudaEventDisableTiming);
        cudaEventCreateWithFlags(&evJ, cudaEventDisableTiming);
        cudaFuncSetAttribute(gat_gemm, cudaFuncAttributeMaxDynamicSharedMemorySize,
                             (128 * 128 + 128 * 256) * 4);
        inited = true;
    }
    const int smem = (128 * 128 + 128 * 256) * 4;  // 192KB

    // Fork: CSR build on s2, overlapped with the GEMM on the main stream.
    cudaEventRecord(evF, 0);
    cudaStreamWaitEvent(s2, evF, 0);
    k_zero<<<(NN + 255) / 256, 256, 0, s2>>>();
    k_count<<<(EE + 255) / 256, 256, 0, s2>>>(ei);
    k_scan<<<1, 1024, 0, s2>>>();
    k_scatter<<<(EE + 255) / 256, 256, 0, s2>>>(ei);
    cudaEventRecord(evJ, s2);

    // Dense part (writes out = fi + self-loop, stashes fj/a1/a2)
    gat_gemm<<<(NN + 127) / 128, 512, smem>>>(X, W1, b1, W2, b2,
                                              wa1, ba1, wa2, ba2, out);

    // Join, then sparse aggregation (no atomics)
    cudaStreamWaitEvent(0, evJ, 0);
    gat_agg<<<(NN + 7) / 8, 256>>>(out);
}

// round 10
// speedup vs baseline: 1.3029x; 1.3029x over previous
#include <cuda_runtime.h>
#include <cuda_fp16.h>

#define NN 50000
#define DD 128
#define EE 800000

// Scratch (allocation-free rule: __device__ globals)
__device__ __half2 g_fjh[NN * 64];   // fj rows in fp16, 64 half2 (=128 cols) per row
__device__ float   g_a1[NN];
__device__ float   g_a2[NN];

__device__ __forceinline__ unsigned long long pack2(float a) {
    unsigned long long r;
    asm("mov.b64 %0, {%1, %1};" : "=l"(r) : "f"(a));
    return r;
}
__device__ __forceinline__ void unpack2(unsigned long long v, float& lo, float& hi) {
    asm("mov.b64 {%0, %1}, %2;" : "=f"(lo), "=f"(hi) : "l"(v));
}
__device__ __forceinline__ unsigned long long ffma2(unsigned long long a,
                                                    unsigned long long b,
                                                    unsigned long long c) {
    unsigned long long d;
    asm("fma.rn.f32x2 %0, %1, %2, %3;" : "=l"(d) : "l"(a), "l"(b), "l"(c));
    return d;
}

// ---------------------------------------------------------------------------
// Kernel 1: fused dense part (R8-proven f32x2 GEMM, at the fp32 roofline).
//   fi = relu(X W1^T + b1), fj = relu(X W2^T + b2)
//   a1 = fi.wa1 + ba1,      a2 = fj.wa2 + ba2
//   out = fi + sigmoid(a1 + a2) * fj   (self-loop folded, fp32)
//   fj stashed as fp16 (half2) for the edge kernel's gather.
// ---------------------------------------------------------------------------
__global__ __launch_bounds__(512, 1) void gat_gemm(
    const float* __restrict__ X,
    const float* __restrict__ W1, const float* __restrict__ b1,
    const float* __restrict__ W2, const float* __restrict__ b2,
    const float* __restrict__ wa1, const float* __restrict__ ba1,
    const float* __restrict__ wa2, const float* __restrict__ ba2,
    float* __restrict__ out)
{
    extern __shared__ float smem[];
    float* sA = smem;              // [128][128]
    float* sB = smem + 128 * 128;  // [128][256] : sB[k][j] = W[j][k]

    const int tid = threadIdx.x;
    const int block_row = blockIdx.x * 128;

    for (int i = tid; i < 128 * 32; i += 512) {
        int row = i >> 5, c4 = i & 31;
        float4 v = make_float4(0.f, 0.f, 0.f, 0.f);
        int grow = block_row + row;
        if (grow < NN) v = ((const float4*)X)[grow * 32 + c4];
        ((float4*)sA)[row * 32 + c4] = v;
    }
    for (int i = tid; i < 128 * 32; i += 512) {
        int j = i & 127;
        int k = (i >> 7) << 2;
        float4 v = ((const float4*)W1)[(j * 128 + k) >> 2];
        sB[(k + 0) * 256 + j] = v.x;
        sB[(k + 1) * 256 + j] = v.y;
        sB[(k + 2) * 256 + j] = v.z;
        sB[(k + 3) * 256 + j] = v.w;
        float4 w = ((const float4*)W2)[(j * 128 + k) >> 2];
        sB[(k + 0) * 256 + 128 + j] = w.x;
        sB[(k + 1) * 256 + 128 + j] = w.y;
        sB[(k + 2) * 256 + 128 + j] = w.z;
        sB[(k + 3) * 256 + 128 + j] = w.w;
    }
    __syncthreads();

    const int tx = tid & 31;
    const int ty = tid >> 5;

    unsigned long long acc[8][4];
    #pragma unroll
    for (int r = 0; r < 8; r++)
        #pragma unroll
        for (int p = 0; p < 4; p++) acc[r][p] = 0ull;

    const float* aBase = sA + (ty * 8) * 128;
    const float* bBase = sB + 2 * tx;

    #pragma unroll 2
    for (int k = 0; k < 128; k += 2) {
        unsigned long long bq0[4], bq1[4];
        #pragma unroll
        for (int p = 0; p < 4; p++) {
            bq0[p] = *(const unsigned long long*)(bBase + (k + 0) * 256 + p * 64);
            bq1[p] = *(const unsigned long long*)(bBase + (k + 1) * 256 + p * 64);
        }
        #pragma unroll
        for (int r = 0; r < 8; r++) {
            float2 av = *(const float2*)(aBase + r * 128 + k);
            unsigned long long a0 = pack2(av.x);
            unsigned long long a1p = pack2(av.y);
            #pragma unroll
            for (int p = 0; p < 4; p++) {
                acc[r][p] = ffma2(a0, bq0[p], acc[r][p]);
                acc[r][p] = ffma2(a1p, bq1[p], acc[r][p]);
            }
        }
    }

    const float vba1 = *ba1;
    const float vba2 = *ba2;
    float wv1[4], wv2[4], bv1[4], bv2[4];
    {
        int c0 = 2 * tx, c1 = 2 * tx + 1, c2 = 64 + 2 * tx, c3 = 65 + 2 * tx;
        wv1[0] = wa1[c0]; wv1[1] = wa1[c1]; wv1[2] = wa1[c2]; wv1[3] = wa1[c3];
        wv2[0] = wa2[c0]; wv2[1] = wa2[c1]; wv2[2] = wa2[c2]; wv2[3] = wa2[c3];
        bv1[0] = b1[c0];  bv1[1] = b1[c1];  bv1[2] = b1[c2];  bv1[3] = b1[c3];
        bv2[0] = b2[c0];  bv2[1] = b2[c1];  bv2[2] = b2[c2];  bv2[3] = b2[c3];
    }

    #pragma unroll
    for (int r = 0; r < 8; r++) {
        int grow = block_row + ty * 8 + r;
        if (grow >= NN) continue;
        float fi[4], fj[4];
        unpack2(acc[r][0], fi[0], fi[1]);
        unpack2(acc[r][1], fi[2], fi[3]);
        unpack2(acc[r][2], fj[0], fj[1]);
        unpack2(acc[r][3], fj[2], fj[3]);
        float pa1 = 0.f, pa2 = 0.f;
        #pragma unroll
        for (int i = 0; i < 4; i++) {
            fi[i] = fmaxf(fi[i] + bv1[i], 0.f);
            fj[i] = fmaxf(fj[i] + bv2[i], 0.f);
            pa1 += fi[i] * wv1[i];
            pa2 += fj[i] * wv2[i];
        }
        #pragma unroll
        for (int off = 16; off > 0; off >>= 1) {
            pa1 += __shfl_xor_sync(0xffffffffu, pa1, off);
            pa2 += __shfl_xor_sync(0xffffffffu, pa2, off);
        }
        float A1 = pa1 + vba1;
        float A2 = pa2 + vba2;
        if (tx == 0) { g_a1[grow] = A1; g_a2[grow] = A2; }
        float att = 1.0f / (1.0f + __expf(-(A1 + A2)));

        float* orow = out + (size_t)grow * DD;
        *(float2*)(orow + 2 * tx)      = make_float2(fi[0] + att * fj[0],
                                                     fi[1] + att * fj[1]);
        *(float2*)(orow + 64 + 2 * tx) = make_float2(fi[2] + att * fj[2],
                                                     fi[3] + att * fj[3]);
        // fp16 stash: this lane owns col pairs (2tx,2tx+1) and (64+2tx,65+2tx)
        __half2* frow = g_fjh + (size_t)grow * 64;
        frow[tx]      = __floats2half2_rn(fj[0], fj[1]);
        frow[32 + tx] = __floats2half2_rn(fj[2], fj[3]);
    }
}

// ---------------------------------------------------------------------------
// Kernel 2: edge scatter, 2 edges per warp (ILP=2), fp16 gather (256B/row),
// fp32 red.global.add.v4 accumulation. fj and out are L2-resident.
// ---------------------------------------------------------------------------
__global__ __launch_bounds__(256) void gat_edge(const int* __restrict__ ei,
                                                float* __restrict__ out)
{
    const int warp = threadIdx.x >> 5;
    const int lane = threadIdx.x & 31;
    const int e0 = (blockIdx.x * 8 + warp) * 2;

    const int r0 = __ldg(ei + e0);
    const int r1 = __ldg(ei + e0 + 1);
    const int c0 = __ldg(ei + EE + e0);
    const int c1 = __ldg(ei + EE + e0 + 1);

    const float s0 = g_a1[r0] + g_a2[c0];
    const float s1 = g_a1[r1] + g_a2[c1];

    // lane loads cols 4*lane .. 4*lane+3 as 2 half2 (8B)
    const uint2 u0 = *(const uint2*)(g_fjh + (size_t)c0 * 64 + lane * 2);
    const uint2 u1 = *(const uint2*)(g_fjh + (size_t)c1 * 64 + lane * 2);

    const float att0 = 1.0f / (1.0f + __expf(-s0));
    const float att1 = 1.0f / (1.0f + __expf(-s1));

    const float2 f0a = __half22float2(*(const __half2*)&u0.x);
    const float2 f0b = __half22float2(*(const __half2*)&u0.y);
    const float2 f1a = __half22float2(*(const __half2*)&u1.x);
    const float2 f1b = __half22float2(*(const __half2*)&u1.y);

    float* p0 = out + (size_t)r0 * DD + lane * 4;
    asm volatile("red.global.add.v4.f32 [%0], {%1, %2, %3, %4};"
                 :: "l"(p0), "f"(att0 * f0a.x), "f"(att0 * f0a.y),
                    "f"(att0 * f0b.x), "f"(att0 * f0b.y)
                 : "memory");
    float* p1 = out + (size_t)r1 * DD + lane * 4;
    asm volatile("red.global.add.v4.f32 [%0], {%1, %2, %3, %4};"
                 :: "l"(p1), "f"(att1 * f1a.x), "f"(att1 * f1a.y),
                    "f"(att1 * f1b.x), "f"(att1 * f1b.y)
                 : "memory");
}

// ---------------------------------------------------------------------------

extern "C" void kernel_launch(void* const* d_in, const int* in_sizes, int n_in,
                              void* d_out, int out_size)
{
    const float* X   = (const float*)d_in[0];
    const float* W1  = (const float*)d_in[1];
    const float* b1  = (const float*)d_in[2];
    const float* W2  = (const float*)d_in[3];
    const float* b2  = (const float*)d_in[4];
    const float* wa1 = (const float*)d_in[5];
    const float* ba1 = (const float*)d_in[6];
    const float* wa2 = (const float*)d_in[7];
    const float* ba2 = (const float*)d_in[8];
    const int*   ei  = (const int*)d_in[9];
    float* out = (float*)d_out;

    const int smem = (128 * 128 + 128 * 256) * 4;  // 192KB
    cudaFuncSetAttribute(gat_gemm, cudaFuncAttributeMaxDynamicSharedMemorySize, smem);

    gat_gemm<<<(NN + 127) / 128, 512, smem>>>(X, W1, b1, W2, b2,
                                              wa1, ba1, wa2, ba2, out);
    gat_edge<<<EE / 16, 256>>>(ei, out);   // 50000 blocks x 8 warps x 2 edges
}